// round 8
// baseline (speedup 1.0000x reference)
#include <cuda_runtime.h>
#include <math.h>

#define NB 16
#define MAX_NODES 100000
#define MAX_EDGES 1250000

typedef unsigned long long u64;

// Scratch (no allocation allowed -> __device__ globals)
__device__ float g_W[128 * 64];      // rows 0..63: W_msg[k][o], rows 64..127: W_self[k][o]
__device__ float g_bias[128];        // [0:64) b_msg, [64:128) b_self
__device__ int   g_cnt[MAX_NODES];
__device__ int   g_off[MAX_NODES + 1];
__device__ int   g_cur[MAX_NODES];
__device__ int   g_elist[MAX_EDGES];

// ---------------- packed f32x2 helpers (Blackwell FFMA2 via PTX) ----------------
__device__ __forceinline__ u64 pack2_dup(float v) {
    u64 r; asm("mov.b64 %0, {%1,%1};" : "=l"(r) : "f"(v)); return r;
}
__device__ __forceinline__ void unpack2(u64 v, float& lo, float& hi) {
    asm("mov.b64 {%0,%1}, %2;" : "=f"(lo), "=f"(hi) : "l"(v));
}
__device__ __forceinline__ u64 ffma2(u64 a, u64 b, u64 c) {
    u64 d; asm("fma.rn.f32x2 %0, %1, %2, %3;" : "=l"(d) : "l"(a), "l"(b), "l"(c)); return d;
}

// ---------------------------------------------------------------------------
// Kernel 1: collapse bases -> W (128x64, k-major) and biases
// ---------------------------------------------------------------------------
__global__ void combine_kernel(const float* __restrict__ wt_msg,
                               const float* __restrict__ b_msg,
                               const float* __restrict__ wt_self,
                               const float* __restrict__ b_self,
                               const float* __restrict__ lin_comb) {
    __shared__ float c[NB];
    if (threadIdx.x < NB) c[threadIdx.x] = lin_comb[threadIdx.x];
    __syncthreads();

    for (int idx = threadIdx.x; idx < 64 * 64; idx += blockDim.x) {
        const float* pm = wt_msg + idx * NB;
        const float* ps = wt_self + idx * NB;
        float am = 0.f, as = 0.f;
#pragma unroll
        for (int b = 0; b < NB; b++) {
            am += pm[b] * c[b];
            as += ps[b] * c[b];
        }
        int i = idx >> 6, o = idx & 63;
        g_W[i * 64 + o] = am;
        g_W[(64 + i) * 64 + o] = as;
    }
    for (int o = threadIdx.x; o < 64; o += blockDim.x) {
        float am = 0.f, as = 0.f;
#pragma unroll
        for (int b = 0; b < NB; b++) {
            am += b_msg[o * NB + b] * c[b];
            as += b_self[o * NB + b] * c[b];
        }
        g_bias[o] = am;
        g_bias[64 + o] = as;
    }
}

// ---------------------------------------------------------------------------
// CSR build: zero counts -> histogram -> single-block scan -> fill edge list
// ---------------------------------------------------------------------------
__global__ void zcnt_kernel(int n_nodes) {
    int i = blockIdx.x * blockDim.x + threadIdx.x;
    if (i < n_nodes) g_cnt[i] = 0;
}

__global__ void count_kernel(const int* __restrict__ ei, int n_edges) {
    int i = blockIdx.x * blockDim.x + threadIdx.x;
    if (i < n_edges) atomicAdd(&g_cnt[ei[n_edges + i]], 1);
}

__global__ void scan_kernel(int n_nodes) {
    __shared__ int part[1024];
    const int t = threadIdx.x;
    const int C = (n_nodes + 1023) >> 10;
    const int lo = t * C;
    const int hi = min(lo + C, n_nodes);

    int s = 0;
    for (int i = lo; i < hi; i++) s += g_cnt[i];
    part[t] = s;
    __syncthreads();

    // Hillis-Steele inclusive scan over 1024 partials
    for (int d = 1; d < 1024; d <<= 1) {
        int v = (t >= d) ? part[t - d] : 0;
        __syncthreads();
        part[t] += v;
        __syncthreads();
    }

    int run = (t == 0) ? 0 : part[t - 1];  // exclusive prefix for this chunk
    for (int i = lo; i < hi; i++) {
        g_off[i] = run;
        g_cur[i] = run;
        run += g_cnt[i];
    }
    if (t == 1023) g_off[n_nodes] = part[1023];
}

__global__ void fill_kernel(const int* __restrict__ ei, int n_edges) {
    int i = blockIdx.x * blockDim.x + threadIdx.x;
    if (i < n_edges) {
        int d = ei[n_edges + i];
        int p = atomicAdd(&g_cur[d], 1);
        g_elist[p] = ei[i];
    }
}

// ---------------------------------------------------------------------------
// Fused kernel: gather-aggregate (CSR) + [S|x] @ [W_msg;W_self] + bias + L2norm
// 256 threads, tile = 128 nodes x 64 cols, K = 128.
// Phase 1: warp w aggregates nodes w*16..w*16+15: each lane sums a float2
//   (k = 2*lane, 2*lane+1) of x[src] over the node's edge list (MLP-4 unroll),
//   writes directly into transposed shA[k][node]; also stages x[node] rows.
// Phase 2: FFMA2 outer-product microkernel (identical to R5's measured one):
//   a operands = adjacent-node packed f32x2 via LDS.64 (conflict-free),
//   W warp-uniform broadcast LDS.128, 16 FFMA2/thread/k.
// ---------------------------------------------------------------------------
#define SA 130

__global__ __launch_bounds__(256, 2)
void fused_kernel(const float* __restrict__ x,
                  float* __restrict__ out,
                  int n_nodes) {
    extern __shared__ float sh[];
    float* shA   = sh;                       // [128][SA]
    float* shW   = sh + 128 * SA;            // [128][64]
    float* s_ss  = shW + 128 * 64;           // [128]
    float* s_inv = s_ss + 128;               // [128]

    const int tid  = threadIdx.x;
    const int lane = tid & 31;
    const int wrp  = tid >> 5;     // 0..7
    const int node0 = blockIdx.x * 128;

    if (tid < 128) s_ss[tid] = 0.f;

    // Stage W (8192 floats, coalesced float4)
    for (int i = tid; i < 2048; i += 256)
        ((float4*)shW)[i] = ((const float4*)g_W)[i];

    // Phase 1: gather-aggregate into transposed shA
    const float2* __restrict__ x2 = (const float2*)x;
#pragma unroll 1
    for (int ni = 0; ni < 16; ni++) {
        const int nl = wrp * 16 + ni;
        const int gn = node0 + nl;
        float2 acc = make_float2(0.f, 0.f);
        float2 xv  = make_float2(0.f, 0.f);
        if (gn < n_nodes) {
            const int beg = g_off[gn];
            const int end = g_off[gn + 1];
            int j = beg;
            for (; j + 4 <= end; j += 4) {
                int s0 = g_elist[j + 0];
                int s1 = g_elist[j + 1];
                int s2 = g_elist[j + 2];
                int s3 = g_elist[j + 3];
                float2 v0 = x2[s0 * 32 + lane];
                float2 v1 = x2[s1 * 32 + lane];
                float2 v2 = x2[s2 * 32 + lane];
                float2 v3 = x2[s3 * 32 + lane];
                acc.x += v0.x + v1.x + v2.x + v3.x;
                acc.y += v0.y + v1.y + v2.y + v3.y;
            }
            for (; j < end; j++) {
                int s = g_elist[j];
                float2 v = x2[s * 32 + lane];
                acc.x += v.x;
                acc.y += v.y;
            }
            xv = x2[gn * 32 + lane];
        }
        shA[(2 * lane + 0) * SA + nl] = acc.x;
        shA[(2 * lane + 1) * SA + nl] = acc.y;
        shA[(64 + 2 * lane + 0) * SA + nl] = xv.x;
        shA[(64 + 2 * lane + 1) * SA + nl] = xv.y;
    }
    __syncthreads();

    // Phase 2: FFMA2 GEMM
    const int col0 = wrp * 8;

    u64 acc[2][8];
#pragma unroll
    for (int q = 0; q < 2; q++)
#pragma unroll
        for (int c = 0; c < 8; c++) acc[q][c] = 0ull;

#pragma unroll 8
    for (int k = 0; k < 128; k++) {
        const float* arow = shA + k * SA + 2 * lane;
        u64 a0 = *(const u64*)(arow);          // nodes 2L, 2L+1
        u64 a1 = *(const u64*)(arow + 64);     // nodes 2L+64, 2L+65
        const float4* wrow = (const float4*)(shW + k * 64 + col0);
        float4 w0 = wrow[0];
        float4 w1 = wrow[1];
        u64 wd0 = pack2_dup(w0.x), wd1 = pack2_dup(w0.y);
        u64 wd2 = pack2_dup(w0.z), wd3 = pack2_dup(w0.w);
        u64 wd4 = pack2_dup(w1.x), wd5 = pack2_dup(w1.y);
        u64 wd6 = pack2_dup(w1.z), wd7 = pack2_dup(w1.w);
        acc[0][0] = ffma2(a0, wd0, acc[0][0]);
        acc[0][1] = ffma2(a0, wd1, acc[0][1]);
        acc[0][2] = ffma2(a0, wd2, acc[0][2]);
        acc[0][3] = ffma2(a0, wd3, acc[0][3]);
        acc[0][4] = ffma2(a0, wd4, acc[0][4]);
        acc[0][5] = ffma2(a0, wd5, acc[0][5]);
        acc[0][6] = ffma2(a0, wd6, acc[0][6]);
        acc[0][7] = ffma2(a0, wd7, acc[0][7]);
        acc[1][0] = ffma2(a1, wd0, acc[1][0]);
        acc[1][1] = ffma2(a1, wd1, acc[1][1]);
        acc[1][2] = ffma2(a1, wd2, acc[1][2]);
        acc[1][3] = ffma2(a1, wd3, acc[1][3]);
        acc[1][4] = ffma2(a1, wd4, acc[1][4]);
        acc[1][5] = ffma2(a1, wd5, acc[1][5]);
        acc[1][6] = ffma2(a1, wd6, acc[1][6]);
        acc[1][7] = ffma2(a1, wd7, acc[1][7]);
    }

    // Unpack: accf[r][c], r=0..3 -> nodes {2L, 2L+1, 2L+64, 2L+65}
    float accf[4][8];
#pragma unroll
    for (int q = 0; q < 2; q++)
#pragma unroll
        for (int c = 0; c < 8; c++)
            unpack2(acc[q][c], accf[2 * q][c], accf[2 * q + 1][c]);

    int nloc[4];
    nloc[0] = 2 * lane; nloc[1] = 2 * lane + 1;
    nloc[2] = 2 * lane + 64; nloc[3] = 2 * lane + 65;

    float bm[8], bsf[8];
#pragma unroll
    for (int c = 0; c < 8; c++) {
        bm[c]  = g_bias[col0 + c];
        bsf[c] = g_bias[64 + col0 + c];
    }

#pragma unroll
    for (int r = 0; r < 4; r++) {
        int gn = node0 + nloc[r];
        float degf = 0.f;
        if (gn < n_nodes) degf = (float)(g_off[gn + 1] - g_off[gn]);
        float ss = 0.f;
#pragma unroll
        for (int c = 0; c < 8; c++) {
            accf[r][c] += degf * bm[c] + bsf[c];
            ss += accf[r][c] * accf[r][c];
        }
        atomicAdd(&s_ss[nloc[r]], ss);
    }
    __syncthreads();

    if (tid < 128) s_inv[tid] = 1.f / fmaxf(sqrtf(s_ss[tid]), 1e-12f);
    __syncthreads();

#pragma unroll
    for (int r = 0; r < 4; r++) {
        int gn = node0 + nloc[r];
        if (gn < n_nodes) {
            float inv = s_inv[nloc[r]];
            float4 o0 = make_float4(accf[r][0] * inv, accf[r][1] * inv,
                                    accf[r][2] * inv, accf[r][3] * inv);
            float4 o1 = make_float4(accf[r][4] * inv, accf[r][5] * inv,
                                    accf[r][6] * inv, accf[r][7] * inv);
            float4* o = (float4*)(out + gn * 64 + col0);
            o[0] = o0;
            o[1] = o1;
        }
    }
}

// ---------------------------------------------------------------------------
// Launch. Inputs (metadata order):
//  0: x [N,64] f32 | 1: edge_index [2,E] i32 | 2: basis_msg_wt [64,64,16]
//  3: basis_msg_bias [64,16] | 4: basis_self_wt | 5: basis_self_bias
//  6: lin_comb [1,16]        out: [N,64] f32
// ---------------------------------------------------------------------------
extern "C" void kernel_launch(void* const* d_in, const int* in_sizes, int n_in,
                              void* d_out, int out_size) {
    const float* x  = (const float*)d_in[0];
    const int*   ei = (const int*)d_in[1];
    const float* wm = (const float*)d_in[2];
    const float* bm = (const float*)d_in[3];
    const float* ws = (const float*)d_in[4];
    const float* bs = (const float*)d_in[5];
    const float* lc = (const float*)d_in[6];
    float* out = (float*)d_out;

    const int n_nodes = in_sizes[0] / 64;
    const int n_edges = in_sizes[1] / 2;

    combine_kernel<<<1, 256>>>(wm, bm, ws, bs, lc);
    zcnt_kernel<<<(n_nodes + 255) / 256, 256>>>(n_nodes);
    count_kernel<<<(n_edges + 255) / 256, 256>>>(ei, n_edges);
    scan_kernel<<<1, 1024>>>(n_nodes);
    fill_kernel<<<(n_edges + 255) / 256, 256>>>(ei, n_edges);

    const int smem = (128 * SA + 128 * 64 + 256) * (int)sizeof(float);  // 100352 B
    cudaFuncSetAttribute(fused_kernel, cudaFuncAttributeMaxDynamicSharedMemorySize, smem);
    fused_kernel<<<(n_nodes + 127) / 128, 256, smem>>>(x, out, n_nodes);
}